// round 8
// baseline (speedup 1.0000x reference)
#include <cuda_runtime.h>
#include <stdint.h>

// Shape fixed for this dataset: B=512 rows, N=16384 residues/row, A atoms/row.
#define N_RES  16384
#define B_MAX  512
#define SPLIT  8
#define SEG    (N_RES / SPLIT)        // 2048 residues per build/write block
#define TPB    256
#define HBINS  2048                   // histogram on key bits 31..21
#define CAP    4096                   // fused-compaction capacity
#define RCAP   2048                   // resolve capacity (==T16 group)

// ---- global scratch (static device allocations; no cudaMalloc) ----
__device__ unsigned short g_key16[(size_t)B_MAX * N_RES];   // 16 MB
__device__ unsigned int   g_hist[(size_t)B_MAX * HBINS];    // 4 MB
__device__ unsigned int   g_T16[B_MAX];

// Order-preserving float->uint transform (total order == IEEE float compare).
__device__ __forceinline__ unsigned int f2key(float f) {
    unsigned int u = __float_as_uint(f);
    return u ^ ((u & 0x80000000u) ? 0xFFFFFFFFu : 0x80000000u);
}

// Exact replica of reference arithmetic (RN, no FMA contraction).
__device__ __forceinline__ unsigned int dist_key(float cx, float cy, float cz,
                                                 float px, float py, float pz,
                                                 float m) {
    float dx = __fsub_rn(cx, px);
    float dy = __fsub_rn(cy, py);
    float dz = __fsub_rn(cz, pz);
    float ss = __fadd_rn(__fadd_rn(__fmul_rn(dx, dx), __fmul_rn(dy, dy)),
                         __fmul_rn(dz, dz));
    float d = __fsqrt_rn(__fadd_rn(ss, 1e-12f));
    d = __fadd_rn(d, __fmul_rn(__fsub_rn(1.0f, m), 1.0e10f));
    return f2key(d);
}

__device__ __forceinline__ void hist_add(unsigned int* hist, unsigned int bin) {
    unsigned int peers = __match_any_sync(0xFFFFFFFFu, bin);
    int leader = __ffs(peers) - 1;
    if ((threadIdx.x & 31) == leader) atomicAdd(&hist[bin], __popc(peers));
}

// Centroid helper: stage atom data to smem in parallel, then strict
// sequential f32 adds in atom order (bit-exact vs reference).
__device__ __forceinline__ void centroid_smem(const float* __restrict__ apos,
                                              const float* __restrict__ amask,
                                              int A, int row, int t,
                                              float* stage,
                                              float* s_cx, float* s_cy, float* s_cz) {
    const float* ap = apos + (size_t)row * A * 3;
    const float* am = amask + (size_t)row * A;
    const bool can_stage = (A * 4 <= 1024);
    if (can_stage) {
        for (int i = t; i < A * 3; i += TPB) stage[i] = ap[i];
        for (int i = t; i < A; i += TPB)     stage[A * 3 + i] = am[i];
    }
    __syncthreads();
    if (t == 0) {
        float sx = 0.f, sy = 0.f, sz = 0.f, smm = 0.f;
        if (can_stage) {
            #pragma unroll 4
            for (int a = 0; a < A; ++a) {
                sx  = __fadd_rn(sx,  stage[a * 3 + 0]);
                sy  = __fadd_rn(sy,  stage[a * 3 + 1]);
                sz  = __fadd_rn(sz,  stage[a * 3 + 2]);
                smm = __fadd_rn(smm, stage[A * 3 + a]);
            }
        } else {
            #pragma unroll 4
            for (int a = 0; a < A; ++a) {
                sx  = __fadd_rn(sx,  ap[a * 3 + 0]);
                sy  = __fadd_rn(sy,  ap[a * 3 + 1]);
                sz  = __fadd_rn(sz,  ap[a * 3 + 2]);
                smm = __fadd_rn(smm, am[a]);
            }
        }
        *s_cx = __fdiv_rn(sx, smm);
        *s_cy = __fdiv_rn(sy, smm);
        *s_cz = __fdiv_rn(sz, smm);
    }
    __syncthreads();
}

// ============================ Kernel A: build ============================
__global__ void __launch_bounds__(TPB)
build_kernel(const float* __restrict__ ca, const float* __restrict__ rmask,
             const float* __restrict__ apos, const float* __restrict__ amask,
             int A)
{
    __shared__ unsigned int hist_s[HBINS];
    __shared__ float stage[1024];
    __shared__ float s_cx, s_cy, s_cz;

    const int row = blockIdx.x / SPLIT;
    const int seg = blockIdx.x % SPLIT;
    const int t = threadIdx.x;

    for (int i = t; i < HBINS; i += TPB) hist_s[i] = 0;
    centroid_smem(apos, amask, A, row, t, stage, &s_cx, &s_cy, &s_cz);
    const float cx = s_cx, cy = s_cy, cz = s_cz;

    const size_t rowoff = (size_t)row * N_RES;
    const float4* ca4 = reinterpret_cast<const float4*>(ca + rowoff * 3);
    const float4* rm4 = reinterpret_cast<const float4*>(rmask + rowoff);
    uint2* kv = reinterpret_cast<uint2*>(g_key16 + rowoff);

    #pragma unroll
    for (int i = 0; i < SEG / 4 / TPB; ++i) {      // 2 iterations
        int g = seg * (SEG / 4) + t + i * TPB;
        float4 v0 = ca4[g * 3 + 0];
        float4 v1 = ca4[g * 3 + 1];
        float4 v2 = ca4[g * 3 + 2];
        float4 m  = rm4[g];
        unsigned int k0 = dist_key(cx, cy, cz, v0.x, v0.y, v0.z, m.x);
        unsigned int k1 = dist_key(cx, cy, cz, v0.w, v1.x, v1.y, m.y);
        unsigned int k2 = dist_key(cx, cy, cz, v1.z, v1.w, v2.x, m.z);
        unsigned int k3 = dist_key(cx, cy, cz, v2.y, v2.z, v2.w, m.w);
        uint2 packed;
        packed.x = (k0 >> 16) | (k1 & 0xFFFF0000u);
        packed.y = (k2 >> 16) | (k3 & 0xFFFF0000u);
        kv[g] = packed;
        hist_add(hist_s, k0 >> 21);
        hist_add(hist_s, k1 >> 21);
        hist_add(hist_s, k2 >> 21);
        hist_add(hist_s, k3 >> 21);
    }
    __syncthreads();

    unsigned int* gh = g_hist + (size_t)row * HBINS;
    for (int i = t; i < HBINS; i += TPB) {
        unsigned int v = hist_s[i];
        if (v) atomicAdd(&gh[i], v);
    }
}

// ============================ Kernel B: select ============================
__global__ void __launch_bounds__(TPB)
select_kernel(const float* __restrict__ ca, const float* __restrict__ rmask,
              const float* __restrict__ apos, const float* __restrict__ amask,
              const int* __restrict__ topk_ptr, int A)
{
    __shared__ unsigned short cand_idx[CAP];   // 8 KB
    __shared__ unsigned int   cand_key[RCAP];  // 8 KB
    __shared__ float stage[1024];
    __shared__ float s_cx, s_cy, s_cz;
    __shared__ unsigned int s_wsum[8];
    __shared__ unsigned int s_sub[32];
    __shared__ int s_b11, s_cb11;
    __shared__ unsigned int s_T16;
    __shared__ int s_cb, s_gsz, s_nc, s_cnt;

    const int row = blockIdx.x;
    const int t = threadIdx.x;
    const size_t rowoff = (size_t)row * N_RES;
    const int kk = *topk_ptr;

    if (kk <= 0 || kk >= N_RES) {
        if (t == 0) g_T16[row] = (kk >= N_RES) ? 0xFFFFu : 0u;
        return;
    }

    if (t < 32) s_sub[t] = 0;
    if (t == 32) s_nc = 0;
    if (t == 33) s_cnt = 0;
    if (t == 34) { s_b11 = 0; s_cb11 = 0; }
    centroid_smem(apos, amask, A, row, t, stage, &s_cx, &s_cy, &s_cz);
    const float cx = s_cx, cy = s_cy, cz = s_cz;

    unsigned short* key16g = g_key16 + rowoff;
    const uint4* kvg = reinterpret_cast<const uint4*>(key16g);   // 2048 uint4

    // ---- scan 2048-bin global histogram: find the 11-bit bin of the k-th key
    {
        const int w = t >> 5, lane = t & 31;
        const uint4* gh4 = reinterpret_cast<const uint4*>(g_hist + (size_t)row * HBINS);
        uint4 h0 = gh4[t * 2];
        uint4 h1 = gh4[t * 2 + 1];
        unsigned int hh[8] = {h0.x, h0.y, h0.z, h0.w, h1.x, h1.y, h1.z, h1.w};
        unsigned int local = 0;
        #pragma unroll
        for (int j = 0; j < 8; ++j) local += hh[j];
        unsigned int incl = local;
        #pragma unroll
        for (int o = 1; o < 32; o <<= 1) {
            unsigned int v = __shfl_up_sync(0xFFFFFFFFu, incl, o);
            if (lane >= o) incl += v;
        }
        if (lane == 31) s_wsum[w] = incl;
        __syncthreads();
        unsigned int pw = 0;
        for (int j = 0; j < w; ++j) pw += s_wsum[j];
        unsigned int pre = pw + incl - local;
        if ((int)pre < kk && (int)(pre + local) >= kk) {
            unsigned int cum = pre;
            #pragma unroll
            for (int j = 0; j < 8; ++j) {
                if ((int)(cum + hh[j]) >= kk) { s_b11 = t * 8 + j; s_cb11 = (int)cum; break; }
                cum += hh[j];
            }
        }
        __syncthreads();
    }

    // ---- fused sub-histogram (5 low bits) + compaction of bin members
    {
        const unsigned int b11 = (unsigned int)s_b11;
        #pragma unroll 2
        for (int q = t; q < N_RES / 8; q += TPB) {
            uint4 v = kvg[q];
            unsigned int xs[8] = {v.x & 0xFFFFu, v.x >> 16, v.y & 0xFFFFu, v.y >> 16,
                                  v.z & 0xFFFFu, v.z >> 16, v.w & 0xFFFFu, v.w >> 16};
            #pragma unroll
            for (int j = 0; j < 8; ++j) {
                if ((xs[j] >> 5) == b11) {
                    atomicAdd(&s_sub[xs[j] & 31u], 1u);
                    int pos = atomicAdd(&s_nc, 1);
                    if (pos < CAP) cand_idx[pos] = (unsigned short)(q * 8 + j);
                }
            }
        }
        __syncthreads();
        if (t == 0) {
            int cum = s_cb11;
            #pragma unroll
            for (int j = 0; j < 32; ++j) {
                int h = (int)s_sub[j];
                if (cum + h >= kk) {
                    s_T16 = ((unsigned int)s_b11 << 5) | (unsigned int)j;
                    s_cb = cum;
                    s_gsz = h;
                    break;
                }
                cum += h;
            }
        }
        __syncthreads();
    }

    const unsigned int T16 = s_T16;
    const int krem = kk - s_cb;
    const bool need_resolve = (krem < s_gsz);

    if (need_resolve) {
        const int nc = s_nc;
        if (nc <= CAP && s_gsz <= RCAP) {
            // ---- warp 0: filter cand list for key16==T16, recompute full keys,
            //      resolve low 16 bits, push out dropped ties in scratch.
            if (t < 32) {
                int m = 0;
                for (int base = 0; base < nc; base += 32) {
                    int i = base + t;
                    unsigned short idx = 0;
                    bool p = false;
                    if (i < nc) {
                        idx = cand_idx[i];
                        p = (key16g[idx] == T16);
                    }
                    unsigned int bal = __ballot_sync(0xFFFFFFFFu, p);
                    int rank = __popc(bal & ((1u << t) - 1u));
                    if (p) {
                        int n = (int)idx;
                        float px = __ldg(ca + (rowoff + n) * 3 + 0);
                        float py = __ldg(ca + (rowoff + n) * 3 + 1);
                        float pz = __ldg(ca + (rowoff + n) * 3 + 2);
                        float mm = __ldg(rmask + rowoff + n);
                        cand_key[m + rank] = dist_key(cx, cy, cz, px, py, pz, mm);
                        cand_idx[m + rank] = idx;
                    }
                    m += __popc(bal);
                    __syncwarp();
                }
                unsigned int P = T16 << 16;
                for (int bit = 15; bit >= 0; --bit) {
                    unsigned int C = P | (1u << bit);
                    int c = 0;
                    for (int i = t; i < m; i += 32) c += (cand_key[i] < C);
                    c = __reduce_add_sync(0xFFFFFFFFu, c);
                    if (c < krem) P = C;
                }
                int cb2 = 0;
                for (int i = t; i < m; i += 32) cb2 += (cand_key[i] < P);
                cb2 = __reduce_add_sync(0xFFFFFFFFu, cb2);
                const int req = krem - cb2;   // # of ==P keys to keep (by index)
                for (int i = t; i < m; i += 32) {
                    unsigned int x = cand_key[i];
                    bool sel;
                    if (x < P) sel = true;
                    else if (x > P) sel = false;
                    else {
                        int rk = 0;
                        unsigned short my = cand_idx[i];
                        for (int j = 0; j < m; ++j)
                            rk += (cand_key[j] == P && cand_idx[j] < my);
                        sel = (rk < req);   // lowest-index ties kept (top_k stable)
                    }
                    if (!sel) key16g[cand_idx[i]] = (unsigned short)0xFFFFu;
                }
            }
        } else {
            // ---- fallback (capacity overflow; effectively never taken): exact.
            unsigned int P = T16 << 16;
            for (int bit = 15; bit >= 0; --bit) {
                if (t == 0) s_cnt = 0;
                __syncthreads();
                unsigned int C = P | (1u << bit);
                int c = 0;
                for (int n = t; n < N_RES; n += TPB) {
                    if (key16g[n] == T16) {
                        float px = __ldg(ca + (rowoff + n) * 3 + 0);
                        float py = __ldg(ca + (rowoff + n) * 3 + 1);
                        float pz = __ldg(ca + (rowoff + n) * 3 + 2);
                        float mm = __ldg(rmask + rowoff + n);
                        c += (dist_key(cx, cy, cz, px, py, pz, mm) < C);
                    }
                }
                c = __reduce_add_sync(0xFFFFFFFFu, c);
                if ((t & 31) == 0) atomicAdd(&s_cnt, c);
                __syncthreads();
                if (s_cnt < krem) P = C;
                __syncthreads();
            }
            if (t == 0) {
                int cb2 = 0;
                for (int n = 0; n < N_RES; ++n) {
                    if (key16g[n] == T16) {
                        float px = ca[(rowoff + n) * 3 + 0];
                        float py = ca[(rowoff + n) * 3 + 1];
                        float pz = ca[(rowoff + n) * 3 + 2];
                        float mm = rmask[rowoff + n];
                        cb2 += (dist_key(cx, cy, cz, px, py, pz, mm) < P);
                    }
                }
                int req = krem - cb2, seen = 0;
                for (int n = 0; n < N_RES; ++n) {
                    if (key16g[n] == T16) {
                        float px = ca[(rowoff + n) * 3 + 0];
                        float py = ca[(rowoff + n) * 3 + 1];
                        float pz = ca[(rowoff + n) * 3 + 2];
                        float mm = rmask[rowoff + n];
                        unsigned int x = dist_key(cx, cy, cz, px, py, pz, mm);
                        if (x > P) key16g[n] = (unsigned short)0xFFFFu;
                        else if (x == P) {
                            ++seen;
                            if (seen > req) key16g[n] = (unsigned short)0xFFFFu;
                        }
                    }
                }
            }
        }
    }
    __syncthreads();
    if (t == 0) g_T16[row] = T16;
}

// ============================ Kernel C: write ============================
__global__ void __launch_bounds__(TPB)
write_kernel(const float* __restrict__ rmask,
             float* __restrict__ out0, float* __restrict__ out1)
{
    const int row = blockIdx.x / SPLIT;
    const int seg = blockIdx.x % SPLIT;
    const unsigned int T16 = g_T16[row];
    const size_t rowoff = (size_t)row * N_RES;
    const uint4*  kv  = reinterpret_cast<const uint4*>(g_key16 + rowoff);
    const float4* rm4 = reinterpret_cast<const float4*>(rmask + rowoff);
    float4* o0 = reinterpret_cast<float4*>(out0 + rowoff);
    float4* o1 = reinterpret_cast<float4*>(out1 + rowoff);

    int q = seg * (SEG / 8) + threadIdx.x;    // one uint4 (8 residues) per thread
    uint4 v = kv[q];
    unsigned int xs[8] = {v.x & 0xFFFFu, v.x >> 16, v.y & 0xFFFFu, v.y >> 16,
                          v.z & 0xFFFFu, v.z >> 16, v.w & 0xFFFFu, v.w >> 16};
    float4 m0 = rm4[q * 2 + 0];
    float4 m1 = rm4[q * 2 + 1];
    float4 a0, a1, b0, b1;
    a0.x = (xs[0] <= T16) ? 0.0f : m0.x;
    a0.y = (xs[1] <= T16) ? 0.0f : m0.y;
    a0.z = (xs[2] <= T16) ? 0.0f : m0.z;
    a0.w = (xs[3] <= T16) ? 0.0f : m0.w;
    a1.x = (xs[4] <= T16) ? 0.0f : m1.x;
    a1.y = (xs[5] <= T16) ? 0.0f : m1.y;
    a1.z = (xs[6] <= T16) ? 0.0f : m1.z;
    a1.w = (xs[7] <= T16) ? 0.0f : m1.w;
    b0.x = (xs[0] <= T16) ? 32.0f : __fsub_rn(1.0f, m0.x);
    b0.y = (xs[1] <= T16) ? 32.0f : __fsub_rn(1.0f, m0.y);
    b0.z = (xs[2] <= T16) ? 32.0f : __fsub_rn(1.0f, m0.z);
    b0.w = (xs[3] <= T16) ? 32.0f : __fsub_rn(1.0f, m0.w);
    b1.x = (xs[4] <= T16) ? 32.0f : __fsub_rn(1.0f, m1.x);
    b1.y = (xs[5] <= T16) ? 32.0f : __fsub_rn(1.0f, m1.y);
    b1.z = (xs[6] <= T16) ? 32.0f : __fsub_rn(1.0f, m1.z);
    b1.w = (xs[7] <= T16) ? 32.0f : __fsub_rn(1.0f, m1.w);
    o0[q * 2 + 0] = a0;
    o0[q * 2 + 1] = a1;
    o1[q * 2 + 0] = b0;
    o1[q * 2 + 1] = b1;
}

extern "C" void kernel_launch(void* const* d_in, const int* in_sizes, int n_in,
                              void* d_out, int out_size) {
    const float* ca    = (const float*)d_in[0];
    const float* rmask = (const float*)d_in[1];
    const float* apos  = (const float*)d_in[2];
    const float* amask = (const float*)d_in[3];
    const int*   topk  = (const int*)d_in[5];   // [ca, rmask, apos, amask, max_p, top_k]

    const int BN = in_sizes[1];          // B * N
    const int B  = BN / N_RES;
    const int A  = (B > 0) ? in_sizes[3] / B : 64;

    float* out0 = (float*)d_out;
    float* out1 = out0 + (size_t)BN;

    void* histAddr = nullptr;
    cudaGetSymbolAddress(&histAddr, g_hist);
    cudaMemsetAsync(histAddr, 0, (size_t)B * HBINS * sizeof(unsigned int));

    build_kernel<<<B * SPLIT, TPB>>>(ca, rmask, apos, amask, A);
    select_kernel<<<B, TPB>>>(ca, rmask, apos, amask, topk, A);
    write_kernel<<<B * SPLIT, TPB>>>(rmask, out0, out1);
}

// round 9
// speedup vs baseline: 1.1314x; 1.1314x over previous
#include <cuda_runtime.h>
#include <stdint.h>

// Shape fixed for this dataset: B=512 rows, N=16384 residues/row, A atoms/row.
#define N_RES  16384
#define B_MAX  512
#define SPLIT  8
#define SEG    (N_RES / SPLIT)        // 2048 residues per build/write block
#define TPB    256
#define HBINS  2048                   // histogram on key bits 31..21
#define CAP    4096                   // fused-compaction capacity
#define RCAP   2048                   // resolve capacity (==T16 group)

// ---- global scratch (static device allocations; no cudaMalloc) ----
__device__ unsigned short g_key16[(size_t)B_MAX * N_RES];   // 16 MB
__device__ unsigned int   g_hist[(size_t)B_MAX * HBINS];    // 4 MB
__device__ unsigned int   g_T16[B_MAX];
__device__ float4         g_cent[B_MAX];
__device__ unsigned int   g_done[B_MAX];

// Order-preserving float->uint transform (total order == IEEE float compare).
__device__ __forceinline__ unsigned int f2key(float f) {
    unsigned int u = __float_as_uint(f);
    return u ^ ((u & 0x80000000u) ? 0xFFFFFFFFu : 0x80000000u);
}

// Exact replica of reference arithmetic (RN, no FMA contraction).
__device__ __forceinline__ unsigned int dist_key(float cx, float cy, float cz,
                                                 float px, float py, float pz,
                                                 float m) {
    float dx = __fsub_rn(cx, px);
    float dy = __fsub_rn(cy, py);
    float dz = __fsub_rn(cz, pz);
    float ss = __fadd_rn(__fadd_rn(__fmul_rn(dx, dx), __fmul_rn(dy, dy)),
                         __fmul_rn(dz, dz));
    float d = __fsqrt_rn(__fadd_rn(ss, 1e-12f));
    d = __fadd_rn(d, __fmul_rn(__fsub_rn(1.0f, m), 1.0e10f));
    return f2key(d);
}

__device__ __forceinline__ void hist_add(unsigned int* hist, unsigned int bin) {
    unsigned int peers = __match_any_sync(0xFFFFFFFFu, bin);
    int leader = __ffs(peers) - 1;
    if ((threadIdx.x & 31) == leader) atomicAdd(&hist[bin], __popc(peers));
}

// ====================== Kernel 0: per-row centroid ======================
__global__ void __launch_bounds__(TPB)
centroid_kernel(const float* __restrict__ apos, const float* __restrict__ amask,
                int A)
{
    __shared__ float stage[2048];
    const int row = blockIdx.x;
    const int t = threadIdx.x;
    const float* ap = apos + (size_t)row * A * 3;
    const float* am = amask + (size_t)row * A;
    const bool can_stage = (A * 4 <= 2048);
    if (can_stage) {
        for (int i = t; i < A * 3; i += TPB) stage[i] = ap[i];
        for (int i = t; i < A; i += TPB)     stage[A * 3 + i] = am[i];
    }
    __syncthreads();
    if (t == 0) {
        float sx = 0.f, sy = 0.f, sz = 0.f, smm = 0.f;
        if (can_stage) {
            #pragma unroll 4
            for (int a = 0; a < A; ++a) {
                sx  = __fadd_rn(sx,  stage[a * 3 + 0]);
                sy  = __fadd_rn(sy,  stage[a * 3 + 1]);
                sz  = __fadd_rn(sz,  stage[a * 3 + 2]);
                smm = __fadd_rn(smm, stage[A * 3 + a]);
            }
        } else {
            #pragma unroll 4
            for (int a = 0; a < A; ++a) {
                sx  = __fadd_rn(sx,  ap[a * 3 + 0]);
                sy  = __fadd_rn(sy,  ap[a * 3 + 1]);
                sz  = __fadd_rn(sz,  ap[a * 3 + 2]);
                smm = __fadd_rn(smm, am[a]);
            }
        }
        float4 c;
        c.x = __fdiv_rn(sx, smm);
        c.y = __fdiv_rn(sy, smm);
        c.z = __fdiv_rn(sz, smm);
        c.w = 0.f;
        g_cent[row] = c;
    }
}

// ============== Kernel 1: build + (last block per row) select ==============
__global__ void __launch_bounds__(TPB)
build_select_kernel(const float* __restrict__ ca, const float* __restrict__ rmask,
                    const int* __restrict__ topk_ptr)
{
    __shared__ unsigned int   hist_s[HBINS];      // 8 KB
    __shared__ unsigned short cand_idx[CAP];      // 8 KB
    __shared__ unsigned int   cand_key[RCAP];     // 8 KB
    __shared__ unsigned int s_wsum[8];
    __shared__ unsigned int s_sub[32];
    __shared__ int s_b11, s_cb11;
    __shared__ unsigned int s_T16;
    __shared__ int s_cb, s_gsz, s_nc, s_last;

    const int row = blockIdx.x / SPLIT;
    const int seg = blockIdx.x % SPLIT;
    const int t = threadIdx.x;
    const size_t rowoff = (size_t)row * N_RES;

    for (int i = t; i < HBINS; i += TPB) hist_s[i] = 0;
    __syncthreads();

    const float4 cent = g_cent[row];
    const float cx = cent.x, cy = cent.y, cz = cent.z;

    const float4* ca4 = reinterpret_cast<const float4*>(ca + rowoff * 3);
    const float4* rm4 = reinterpret_cast<const float4*>(rmask + rowoff);
    uint2* kv = reinterpret_cast<uint2*>(g_key16 + rowoff);

    #pragma unroll
    for (int i = 0; i < SEG / 4 / TPB; ++i) {      // 2 iterations
        int g = seg * (SEG / 4) + t + i * TPB;
        float4 v0 = ca4[g * 3 + 0];
        float4 v1 = ca4[g * 3 + 1];
        float4 v2 = ca4[g * 3 + 2];
        float4 m  = rm4[g];
        unsigned int k0 = dist_key(cx, cy, cz, v0.x, v0.y, v0.z, m.x);
        unsigned int k1 = dist_key(cx, cy, cz, v0.w, v1.x, v1.y, m.y);
        unsigned int k2 = dist_key(cx, cy, cz, v1.z, v1.w, v2.x, m.z);
        unsigned int k3 = dist_key(cx, cy, cz, v2.y, v2.z, v2.w, m.w);
        uint2 packed;
        packed.x = (k0 >> 16) | (k1 & 0xFFFF0000u);
        packed.y = (k2 >> 16) | (k3 & 0xFFFF0000u);
        kv[g] = packed;
        hist_add(hist_s, k0 >> 21);
        hist_add(hist_s, k1 >> 21);
        hist_add(hist_s, k2 >> 21);
        hist_add(hist_s, k3 >> 21);
    }
    __syncthreads();

    // flush block-local histogram into the row's global histogram
    unsigned int* gh = g_hist + (size_t)row * HBINS;
    for (int i = t; i < HBINS; i += TPB) {
        unsigned int v = hist_s[i];
        if (v) atomicAdd(&gh[i], v);
    }

    // release: all key16 + hist writes visible before counter bump
    __threadfence();
    if (t == 0) {
        unsigned int old = atomicAdd(&g_done[row], 1u);
        s_last = (old == SPLIT - 1) ? 1 : 0;
    }
    __syncthreads();
    if (!s_last) return;
    __threadfence();   // acquire: see all segments' key16 + hist writes

    // ======================= SELECT (last block only) =======================
    const int kk = *topk_ptr;
    if (kk <= 0 || kk >= N_RES) {
        if (t == 0) g_T16[row] = (kk >= N_RES) ? 0xFFFFu : 0u;
        return;
    }

    if (t < 32) s_sub[t] = 0;
    if (t == 32) s_nc = 0;
    if (t == 33) { s_b11 = 0; s_cb11 = 0; }
    __syncthreads();

    unsigned short* key16g = g_key16 + rowoff;
    const uint4* kvg = reinterpret_cast<const uint4*>(key16g);   // 2048 uint4

    // ---- scan 2048-bin global histogram: find the 11-bit bin of the k-th key
    {
        const int w = t >> 5, lane = t & 31;
        const uint4* gh4 = reinterpret_cast<const uint4*>(gh);
        uint4 h0 = gh4[t * 2];
        uint4 h1 = gh4[t * 2 + 1];
        unsigned int hh[8] = {h0.x, h0.y, h0.z, h0.w, h1.x, h1.y, h1.z, h1.w};
        unsigned int local = 0;
        #pragma unroll
        for (int j = 0; j < 8; ++j) local += hh[j];
        unsigned int incl = local;
        #pragma unroll
        for (int o = 1; o < 32; o <<= 1) {
            unsigned int v = __shfl_up_sync(0xFFFFFFFFu, incl, o);
            if (lane >= o) incl += v;
        }
        if (lane == 31) s_wsum[w] = incl;
        __syncthreads();
        unsigned int pw = 0;
        for (int j = 0; j < w; ++j) pw += s_wsum[j];
        unsigned int pre = pw + incl - local;
        if ((int)pre < kk && (int)(pre + local) >= kk) {
            unsigned int cum = pre;
            #pragma unroll
            for (int j = 0; j < 8; ++j) {
                if ((int)(cum + hh[j]) >= kk) { s_b11 = t * 8 + j; s_cb11 = (int)cum; break; }
                cum += hh[j];
            }
        }
        __syncthreads();
    }

    // ---- fused sub-histogram (5 low bits) + compaction of bin members
    {
        const unsigned int b11 = (unsigned int)s_b11;
        #pragma unroll 2
        for (int q = t; q < N_RES / 8; q += TPB) {
            uint4 v = kvg[q];
            unsigned int xs[8] = {v.x & 0xFFFFu, v.x >> 16, v.y & 0xFFFFu, v.y >> 16,
                                  v.z & 0xFFFFu, v.z >> 16, v.w & 0xFFFFu, v.w >> 16};
            #pragma unroll
            for (int j = 0; j < 8; ++j) {
                if ((xs[j] >> 5) == b11) {
                    atomicAdd(&s_sub[xs[j] & 31u], 1u);
                    int pos = atomicAdd(&s_nc, 1);
                    if (pos < CAP) cand_idx[pos] = (unsigned short)(q * 8 + j);
                }
            }
        }
        __syncthreads();
        if (t == 0) {
            int cum = s_cb11;
            #pragma unroll
            for (int j = 0; j < 32; ++j) {
                int h = (int)s_sub[j];
                if (cum + h >= kk) {
                    s_T16 = ((unsigned int)s_b11 << 5) | (unsigned int)j;
                    s_cb = cum;
                    s_gsz = h;
                    break;
                }
                cum += h;
            }
        }
        __syncthreads();
    }

    const unsigned int T16 = s_T16;
    const int krem = kk - s_cb;
    const bool need_resolve = (krem < s_gsz);

    if (need_resolve) {
        const int nc = s_nc;
        if (nc <= CAP && s_gsz <= RCAP) {
            // ---- warp 0: filter cand list for key16==T16, recompute full keys,
            //      resolve low 16 bits, push out dropped ties in scratch.
            if (t < 32) {
                int m = 0;
                for (int base = 0; base < nc; base += 32) {
                    int i = base + t;
                    unsigned short idx = 0;
                    bool p = false;
                    if (i < nc) {
                        idx = cand_idx[i];
                        p = (key16g[idx] == T16);
                    }
                    unsigned int bal = __ballot_sync(0xFFFFFFFFu, p);
                    int rank = __popc(bal & ((1u << t) - 1u));
                    if (p) {
                        int n = (int)idx;
                        float px = __ldg(ca + (rowoff + n) * 3 + 0);
                        float py = __ldg(ca + (rowoff + n) * 3 + 1);
                        float pz = __ldg(ca + (rowoff + n) * 3 + 2);
                        float mm = __ldg(rmask + rowoff + n);
                        cand_key[m + rank] = dist_key(cx, cy, cz, px, py, pz, mm);
                        cand_idx[m + rank] = idx;
                    }
                    m += __popc(bal);
                    __syncwarp();
                }
                unsigned int P = T16 << 16;
                for (int bit = 15; bit >= 0; --bit) {
                    unsigned int C = P | (1u << bit);
                    int c = 0;
                    for (int i = t; i < m; i += 32) c += (cand_key[i] < C);
                    c = __reduce_add_sync(0xFFFFFFFFu, c);
                    if (c < krem) P = C;
                }
                int cb2 = 0;
                for (int i = t; i < m; i += 32) cb2 += (cand_key[i] < P);
                cb2 = __reduce_add_sync(0xFFFFFFFFu, cb2);
                const int req = krem - cb2;   // # of ==P keys to keep (by index)
                for (int i = t; i < m; i += 32) {
                    unsigned int x = cand_key[i];
                    bool sel;
                    if (x < P) sel = true;
                    else if (x > P) sel = false;
                    else {
                        int rk = 0;
                        unsigned short my = cand_idx[i];
                        for (int j = 0; j < m; ++j)
                            rk += (cand_key[j] == P && cand_idx[j] < my);
                        sel = (rk < req);   // lowest-index ties kept (top_k stable)
                    }
                    if (!sel) key16g[cand_idx[i]] = (unsigned short)0xFFFFu;
                }
            }
        } else {
            // ---- fallback (capacity overflow; effectively never taken): exact,
            //      t0-serial over the ==T16 group, recomputing full keys.
            if (t == 0) {
                // collect and resolve serially (group is pathological but finite)
                unsigned int P = T16 << 16;
                for (int bit = 15; bit >= 0; --bit) {
                    unsigned int C = P | (1u << bit);
                    int c = 0;
                    for (int n = 0; n < N_RES; ++n) {
                        if (key16g[n] == T16) {
                            float px = ca[(rowoff + n) * 3 + 0];
                            float py = ca[(rowoff + n) * 3 + 1];
                            float pz = ca[(rowoff + n) * 3 + 2];
                            float mm = rmask[rowoff + n];
                            c += (dist_key(cx, cy, cz, px, py, pz, mm) < C);
                        }
                    }
                    if (c < krem) P = C;
                }
                int cb2 = 0;
                for (int n = 0; n < N_RES; ++n) {
                    if (key16g[n] == T16) {
                        float px = ca[(rowoff + n) * 3 + 0];
                        float py = ca[(rowoff + n) * 3 + 1];
                        float pz = ca[(rowoff + n) * 3 + 2];
                        float mm = rmask[rowoff + n];
                        cb2 += (dist_key(cx, cy, cz, px, py, pz, mm) < P);
                    }
                }
                int req = krem - cb2, seen = 0;
                for (int n = 0; n < N_RES; ++n) {
                    if (key16g[n] == T16) {
                        float px = ca[(rowoff + n) * 3 + 0];
                        float py = ca[(rowoff + n) * 3 + 1];
                        float pz = ca[(rowoff + n) * 3 + 2];
                        float mm = rmask[rowoff + n];
                        unsigned int x = dist_key(cx, cy, cz, px, py, pz, mm);
                        if (x > P) key16g[n] = (unsigned short)0xFFFFu;
                        else if (x == P) {
                            ++seen;
                            if (seen > req) key16g[n] = (unsigned short)0xFFFFu;
                        }
                    }
                }
            }
        }
    }
    __syncthreads();
    if (t == 0) g_T16[row] = T16;
}

// ============================ Kernel 2: write ============================
__global__ void __launch_bounds__(TPB)
write_kernel(const float* __restrict__ rmask,
             float* __restrict__ out0, float* __restrict__ out1)
{
    const int row = blockIdx.x / SPLIT;
    const int seg = blockIdx.x % SPLIT;
    const unsigned int T16 = g_T16[row];
    const size_t rowoff = (size_t)row * N_RES;
    const uint4*  kv  = reinterpret_cast<const uint4*>(g_key16 + rowoff);
    const float4* rm4 = reinterpret_cast<const float4*>(rmask + rowoff);
    float4* o0 = reinterpret_cast<float4*>(out0 + rowoff);
    float4* o1 = reinterpret_cast<float4*>(out1 + rowoff);

    int q = seg * (SEG / 8) + threadIdx.x;    // one uint4 (8 residues) per thread
    uint4 v = kv[q];
    unsigned int xs[8] = {v.x & 0xFFFFu, v.x >> 16, v.y & 0xFFFFu, v.y >> 16,
                          v.z & 0xFFFFu, v.z >> 16, v.w & 0xFFFFu, v.w >> 16};
    float4 m0 = rm4[q * 2 + 0];
    float4 m1 = rm4[q * 2 + 1];
    float4 a0, a1, b0, b1;
    a0.x = (xs[0] <= T16) ? 0.0f : m0.x;
    a0.y = (xs[1] <= T16) ? 0.0f : m0.y;
    a0.z = (xs[2] <= T16) ? 0.0f : m0.z;
    a0.w = (xs[3] <= T16) ? 0.0f : m0.w;
    a1.x = (xs[4] <= T16) ? 0.0f : m1.x;
    a1.y = (xs[5] <= T16) ? 0.0f : m1.y;
    a1.z = (xs[6] <= T16) ? 0.0f : m1.z;
    a1.w = (xs[7] <= T16) ? 0.0f : m1.w;
    b0.x = (xs[0] <= T16) ? 32.0f : __fsub_rn(1.0f, m0.x);
    b0.y = (xs[1] <= T16) ? 32.0f : __fsub_rn(1.0f, m0.y);
    b0.z = (xs[2] <= T16) ? 32.0f : __fsub_rn(1.0f, m0.z);
    b0.w = (xs[3] <= T16) ? 32.0f : __fsub_rn(1.0f, m0.w);
    b1.x = (xs[4] <= T16) ? 32.0f : __fsub_rn(1.0f, m1.x);
    b1.y = (xs[5] <= T16) ? 32.0f : __fsub_rn(1.0f, m1.y);
    b1.z = (xs[6] <= T16) ? 32.0f : __fsub_rn(1.0f, m1.z);
    b1.w = (xs[7] <= T16) ? 32.0f : __fsub_rn(1.0f, m1.w);
    o0[q * 2 + 0] = a0;
    o0[q * 2 + 1] = a1;
    o1[q * 2 + 0] = b0;
    o1[q * 2 + 1] = b1;
}

extern "C" void kernel_launch(void* const* d_in, const int* in_sizes, int n_in,
                              void* d_out, int out_size) {
    const float* ca    = (const float*)d_in[0];
    const float* rmask = (const float*)d_in[1];
    const float* apos  = (const float*)d_in[2];
    const float* amask = (const float*)d_in[3];
    const int*   topk  = (const int*)d_in[5];   // [ca, rmask, apos, amask, max_p, top_k]

    const int BN = in_sizes[1];          // B * N
    const int B  = BN / N_RES;
    const int A  = (B > 0) ? in_sizes[3] / B : 64;

    float* out0 = (float*)d_out;
    float* out1 = out0 + (size_t)BN;

    void* histAddr = nullptr; void* doneAddr = nullptr;
    cudaGetSymbolAddress(&histAddr, g_hist);
    cudaGetSymbolAddress(&doneAddr, g_done);
    cudaMemsetAsync(histAddr, 0, (size_t)B * HBINS * sizeof(unsigned int));
    cudaMemsetAsync(doneAddr, 0, (size_t)B * sizeof(unsigned int));

    centroid_kernel<<<B, TPB>>>(apos, amask, A);
    build_select_kernel<<<B * SPLIT, TPB>>>(ca, rmask, topk);
    write_kernel<<<B * SPLIT, TPB>>>(rmask, out0, out1);
}